// round 1
// baseline (speedup 1.0000x reference)
#include <cuda_runtime.h>
#include <math.h>

#define DD 128
#define KK 32
#define NMAX 50000

// Scratch (allocation-free rule: __device__ globals)
__device__ float g_x[NMAX * DD];     // prep output (tangent-space features * mask)
__device__ float g_msg[NMAX * DD];   // GEMM output (messages)

// ---------------------------------------------------------------------------
// Prep: y = (do_logmap ? logmap0(x) : x) * mask      (one warp per row)
// ---------------------------------------------------------------------------
__global__ void prep_kernel(const float* __restrict__ xin,
                            const float* __restrict__ mask,
                            float* __restrict__ xout,
                            int N, int do_logmap) {
    int warp = (blockIdx.x * blockDim.x + threadIdx.x) >> 5;
    int lane = threadIdx.x & 31;
    if (warp >= N) return;

    float4 v = *(const float4*)(xin + (size_t)warp * DD + lane * 4);
    float scale = mask[warp];
    if (do_logmap) {
        float s = v.x * v.x + v.y * v.y + v.z * v.z + v.w * v.w;
        #pragma unroll
        for (int o = 16; o > 0; o >>= 1) s += __shfl_xor_sync(0xffffffffu, s, o);
        float n  = sqrtf(s);
        float nc = fminf(fmaxf(n, 1e-5f), 1.0f - 1e-5f);
        scale *= atanhf(nc) / fmaxf(n, 1e-5f);
    }
    float4 o;
    o.x = v.x * scale; o.y = v.y * scale; o.z = v.z * scale; o.w = v.w * scale;
    *(float4*)(xout + (size_t)warp * DD + lane * 4) = o;
}

// ---------------------------------------------------------------------------
// GEMM: C[N,128] = A[N,128] @ W[128,128], epilogue * mask[row]
// Block tile 128x128, BK=32. Thread tile 8x8 arranged as 2x2 blocks of 4x4
// (rows {r0..r0+3, r0+64..r0+67}, cols {c0..c0+3, c0+64..c0+67}) so all
// shared loads are lane-contiguous float4 (conflict-free).
// ---------------------------------------------------------------------------
__global__ __launch_bounds__(256, 2)
void gemm_kernel(const float* __restrict__ A,
                 const float* __restrict__ W,
                 const float* __restrict__ mask,
                 float* __restrict__ C,
                 int N) {
    __shared__ float As[32][128];   // [k][row]  (transposed)
    __shared__ float Ws[32][128];   // [k][col]

    int tid = threadIdx.x;
    int block_row = blockIdx.x * 128;

    int r0 = (tid >> 4) * 4;        // 0..60
    int c0 = (tid & 15) * 4;        // 0..60

    float acc[8][8];
    #pragma unroll
    for (int i = 0; i < 8; i++)
        #pragma unroll
        for (int j = 0; j < 8; j++) acc[i][j] = 0.f;

    for (int k0 = 0; k0 < 128; k0 += 32) {
        // Load A tile: 128 rows x 32 k -> As[k][row]. 1024 float4, 4/thread.
        #pragma unroll
        for (int i = 0; i < 4; i++) {
            int idx  = tid + i * 256;       // 0..1023
            int row  = idx >> 3;            // 0..127
            int c4   = idx & 7;             // which float4 of the 32-k chunk
            int grow = block_row + row;
            float4 v = make_float4(0.f, 0.f, 0.f, 0.f);
            if (grow < N)
                v = *(const float4*)(A + (size_t)grow * 128 + k0 + c4 * 4);
            As[c4 * 4 + 0][row] = v.x;
            As[c4 * 4 + 1][row] = v.y;
            As[c4 * 4 + 2][row] = v.z;
            As[c4 * 4 + 3][row] = v.w;
        }
        // Load W tile: k0..k0+31 rows x 128 cols. 1024 float4, 4/thread.
        #pragma unroll
        for (int i = 0; i < 4; i++) {
            int idx = tid + i * 256;
            int kr  = idx >> 5;             // 0..31
            int c4  = idx & 31;             // 0..31
            *(float4*)&Ws[kr][c4 * 4] =
                *(const float4*)(W + (size_t)(k0 + kr) * 128 + c4 * 4);
        }
        __syncthreads();

        #pragma unroll
        for (int k = 0; k < 32; k++) {
            float a[8], b[8];
            *(float4*)(a + 0) = *(float4*)&As[k][r0];
            *(float4*)(a + 4) = *(float4*)&As[k][r0 + 64];
            *(float4*)(b + 0) = *(float4*)&Ws[k][c0];
            *(float4*)(b + 4) = *(float4*)&Ws[k][c0 + 64];
            #pragma unroll
            for (int i = 0; i < 8; i++)
                #pragma unroll
                for (int j = 0; j < 8; j++)
                    acc[i][j] = fmaf(a[i], b[j], acc[i][j]);
        }
        __syncthreads();
    }

    // Epilogue: * mask[row], write float4 pairs
    #pragma unroll
    for (int i = 0; i < 8; i++) {
        int rloc = (i < 4) ? (r0 + i) : (r0 + 64 + (i - 4));
        int grow = block_row + rloc;
        if (grow >= N) continue;
        float m = mask[grow];
        float4 o0, o1;
        o0.x = acc[i][0] * m; o0.y = acc[i][1] * m;
        o0.z = acc[i][2] * m; o0.w = acc[i][3] * m;
        o1.x = acc[i][4] * m; o1.y = acc[i][5] * m;
        o1.z = acc[i][6] * m; o1.w = acc[i][7] * m;
        *(float4*)(C + (size_t)grow * 128 + c0)      = o0;
        *(float4*)(C + (size_t)grow * 128 + c0 + 64) = o1;
    }
}

// ---------------------------------------------------------------------------
// Gather + weighted sum + exp-map + ReLU.  One warp per node; lane owns a
// float4 column slice. combined = mask * sum_k w[k] * msg[adj[k]];
// x = relu(expmap0(combined) * mask) * mask
// ---------------------------------------------------------------------------
__global__ void gather_kernel(const int*   __restrict__ adj,
                              const float* __restrict__ wgt,
                              const float* __restrict__ mask,
                              const float* __restrict__ msg,
                              float* __restrict__ xout,
                              int N) {
    int warp = (blockIdx.x * blockDim.x + threadIdx.x) >> 5;
    int lane = threadIdx.x & 31;
    if (warp >= N) return;

    int   a = adj[(size_t)warp * KK + lane];
    float w = wgt[(size_t)warp * KK + lane];

    float4 acc = make_float4(0.f, 0.f, 0.f, 0.f);
    #pragma unroll
    for (int k = 0; k < KK; k++) {
        int   j  = __shfl_sync(0xffffffffu, a, k);
        float wk = __shfl_sync(0xffffffffu, w, k);
        float4 m = *(const float4*)(msg + (size_t)j * DD + lane * 4);
        acc.x = fmaf(wk, m.x, acc.x);
        acc.y = fmaf(wk, m.y, acc.y);
        acc.z = fmaf(wk, m.z, acc.z);
        acc.w = fmaf(wk, m.w, acc.w);
    }

    float mk = mask[warp];
    acc.x *= mk; acc.y *= mk; acc.z *= mk; acc.w *= mk;   // combined

    float s = acc.x * acc.x + acc.y * acc.y + acc.z * acc.z + acc.w * acc.w;
    #pragma unroll
    for (int o = 16; o > 0; o >>= 1) s += __shfl_xor_sync(0xffffffffu, s, o);
    float n  = sqrtf(s);
    float nc = fminf(fmaxf(n, 1e-5f), 15.0f);
    float scale = tanhf(nc) / fmaxf(n, 1e-5f) * mk;       // expmap * mask

    float4 o;
    o.x = fmaxf(acc.x * scale, 0.f) * mk;
    o.y = fmaxf(acc.y * scale, 0.f) * mk;
    o.z = fmaxf(acc.z * scale, 0.f) * mk;
    o.w = fmaxf(acc.w * scale, 0.f) * mk;
    *(float4*)(xout + (size_t)warp * DD + lane * 4) = o;
}

// ---------------------------------------------------------------------------
extern "C" void kernel_launch(void* const* d_in, const int* in_sizes, int n_in,
                              void* d_out, int out_size) {
    const float* node_repr = (const float*)d_in[0];
    const int*   adj       = (const int*)  d_in[1];
    const float* weight    = (const float*)d_in[2];
    const float* mask      = (const float*)d_in[3];
    const float* msg_w     = (const float*)d_in[4];

    int N = in_sizes[0] / DD;
    float* out = (float*)d_out;

    float* xbuf;
    float* mbuf;
    cudaGetSymbolAddress((void**)&xbuf, g_x);
    cudaGetSymbolAddress((void**)&mbuf, g_msg);

    int warpBlocks = (N * 32 + 255) / 256;      // warp-per-row kernels
    int gemmBlocks = (N + 127) / 128;

    // ---- Layer 0 ----
    prep_kernel<<<warpBlocks, 256>>>(node_repr, mask, xbuf, N, 0);
    gemm_kernel<<<gemmBlocks, 256>>>(xbuf, msg_w, mask, mbuf, N);
    gather_kernel<<<warpBlocks, 256>>>(adj, weight, mask, mbuf, out, N);

    // ---- Layer 1 ----
    prep_kernel<<<warpBlocks, 256>>>(out, mask, xbuf, N, 1);
    gemm_kernel<<<gemmBlocks, 256>>>(xbuf, msg_w + DD * DD, mask, mbuf, N);
    gather_kernel<<<warpBlocks, 256>>>(adj, weight, mask, mbuf, out, N);
}

// round 2
// speedup vs baseline: 1.8690x; 1.8690x over previous
#include <cuda_runtime.h>
#include <cuda_fp16.h>
#include <math.h>

#define DD 128
#define KK 32
#define NMAX 50000

// Scratch (allocation-free rule: __device__ globals)
__device__ float  g_x[NMAX * DD];     // tangent-space features for layer-1 GEMM
__device__ __half g_msg[NMAX * DD];   // GEMM output (messages), fp16 to halve gather traffic

// ---------------------------------------------------------------------------
// GEMM: C[N,128] = (A[N,128] * rowscale) @ W[128,128], epilogue * mask[row],
// output stored as fp16. Block tile 128x128, BK=32, 8x8 thread tile as 2x2
// blocks of 4x4 (conflict-free float4 shared loads).
// SCALE_A: multiply A rows by mask[row] on load (replaces layer-0 prep).
// ---------------------------------------------------------------------------
template <bool SCALE_A>
__global__ __launch_bounds__(256, 2)
void gemm_kernel(const float* __restrict__ A,
                 const float* __restrict__ W,
                 const float* __restrict__ mask,
                 __half* __restrict__ C,
                 int N) {
    __shared__ float As[32][128];   // [k][row]  (transposed)
    __shared__ float Ws[32][128];   // [k][col]

    int tid = threadIdx.x;
    int block_row = blockIdx.x * 128;

    int r0 = (tid >> 4) * 4;        // 0..60
    int c0 = (tid & 15) * 4;        // 0..60

    float acc[8][8];
    #pragma unroll
    for (int i = 0; i < 8; i++)
        #pragma unroll
        for (int j = 0; j < 8; j++) acc[i][j] = 0.f;

    for (int k0 = 0; k0 < 128; k0 += 32) {
        // A tile: 128 rows x 32 k -> As[k][row]. 1024 float4, 4/thread.
        #pragma unroll
        for (int i = 0; i < 4; i++) {
            int idx  = tid + i * 256;       // 0..1023
            int row  = idx >> 3;            // 0..127
            int c4   = idx & 7;             // float4 index within 32-k chunk
            int grow = block_row + row;
            float4 v = make_float4(0.f, 0.f, 0.f, 0.f);
            if (grow < N) {
                v = *(const float4*)(A + (size_t)grow * 128 + k0 + c4 * 4);
                if (SCALE_A) {
                    float m = mask[grow];
                    v.x *= m; v.y *= m; v.z *= m; v.w *= m;
                }
            }
            As[c4 * 4 + 0][row] = v.x;
            As[c4 * 4 + 1][row] = v.y;
            As[c4 * 4 + 2][row] = v.z;
            As[c4 * 4 + 3][row] = v.w;
        }
        // W tile: 32 k x 128 cols. 1024 float4, 4/thread.
        #pragma unroll
        for (int i = 0; i < 4; i++) {
            int idx = tid + i * 256;
            int kr  = idx >> 5;
            int c4  = idx & 31;
            *(float4*)&Ws[kr][c4 * 4] =
                *(const float4*)(W + (size_t)(k0 + kr) * 128 + c4 * 4);
        }
        __syncthreads();

        #pragma unroll
        for (int k = 0; k < 32; k++) {
            float a[8], b[8];
            *(float4*)(a + 0) = *(float4*)&As[k][r0];
            *(float4*)(a + 4) = *(float4*)&As[k][r0 + 64];
            *(float4*)(b + 0) = *(float4*)&Ws[k][c0];
            *(float4*)(b + 4) = *(float4*)&Ws[k][c0 + 64];
            #pragma unroll
            for (int i = 0; i < 8; i++)
                #pragma unroll
                for (int j = 0; j < 8; j++)
                    acc[i][j] = fmaf(a[i], b[j], acc[i][j]);
        }
        __syncthreads();
    }

    // Epilogue: * mask[row], convert to fp16, 8-byte stores
    #pragma unroll
    for (int i = 0; i < 8; i++) {
        int rloc = (i < 4) ? (r0 + i) : (r0 + 64 + (i - 4));
        int grow = block_row + rloc;
        if (grow >= N) continue;
        float m = mask[grow];
        __half2 h[4];
        h[0] = __floats2half2_rn(acc[i][0] * m, acc[i][1] * m);
        h[1] = __floats2half2_rn(acc[i][2] * m, acc[i][3] * m);
        h[2] = __floats2half2_rn(acc[i][4] * m, acc[i][5] * m);
        h[3] = __floats2half2_rn(acc[i][6] * m, acc[i][7] * m);
        __half* Crow = C + (size_t)grow * 128;
        *(uint2*)(Crow + c0)      = *(uint2*)&h[0];
        *(uint2*)(Crow + c0 + 64) = *(uint2*)&h[2];
    }
}

// ---------------------------------------------------------------------------
// Gather (fp16 msg) + weighted sum + exp-map + ReLU [+ fused log-map of the
// next layer's prep when FUSE_LOGMAP]. One warp per node; lane owns 4 columns.
// ---------------------------------------------------------------------------
template <bool FUSE_LOGMAP>
__global__ void gather_kernel(const int*    __restrict__ adj,
                              const float*  __restrict__ wgt,
                              const float*  __restrict__ mask,
                              const __half* __restrict__ msg,
                              float* __restrict__ xout,
                              int N) {
    int warp = (blockIdx.x * blockDim.x + threadIdx.x) >> 5;
    int lane = threadIdx.x & 31;
    if (warp >= N) return;

    int   a = adj[(size_t)warp * KK + lane];
    float w = wgt[(size_t)warp * KK + lane];

    float acc0 = 0.f, acc1 = 0.f, acc2 = 0.f, acc3 = 0.f;
    #pragma unroll
    for (int k = 0; k < KK; k++) {
        int   j  = __shfl_sync(0xffffffffu, a, k);
        float wk = __shfl_sync(0xffffffffu, w, k);
        uint2 raw = *(const uint2*)(msg + (size_t)j * DD + lane * 4);
        float2 f0 = __half22float2(*(__half2*)&raw.x);
        float2 f1 = __half22float2(*(__half2*)&raw.y);
        acc0 = fmaf(wk, f0.x, acc0);
        acc1 = fmaf(wk, f0.y, acc1);
        acc2 = fmaf(wk, f1.x, acc2);
        acc3 = fmaf(wk, f1.y, acc3);
    }

    float mk = mask[warp];
    acc0 *= mk; acc1 *= mk; acc2 *= mk; acc3 *= mk;   // combined

    // exp-map at origin
    float s = acc0 * acc0 + acc1 * acc1 + acc2 * acc2 + acc3 * acc3;
    #pragma unroll
    for (int o = 16; o > 0; o >>= 1) s += __shfl_xor_sync(0xffffffffu, s, o);
    float n  = sqrtf(s);
    float nc = fminf(fmaxf(n, 1e-5f), 15.0f);
    float scale = tanhf(nc) / fmaxf(n, 1e-5f) * mk;   // expmap * mask

    float x0 = fmaxf(acc0 * scale, 0.f) * mk;         // relu * mask
    float x1 = fmaxf(acc1 * scale, 0.f) * mk;
    float x2 = fmaxf(acc2 * scale, 0.f) * mk;
    float x3 = fmaxf(acc3 * scale, 0.f) * mk;

    if (FUSE_LOGMAP) {
        // next layer's prep: logmap0(x) * mask
        float s2 = x0 * x0 + x1 * x1 + x2 * x2 + x3 * x3;
        #pragma unroll
        for (int o = 16; o > 0; o >>= 1) s2 += __shfl_xor_sync(0xffffffffu, s2, o);
        float n2  = sqrtf(s2);
        float nc2 = fminf(fmaxf(n2, 1e-5f), 1.0f - 1e-5f);
        float ls  = atanhf(nc2) / fmaxf(n2, 1e-5f) * mk;
        x0 *= ls; x1 *= ls; x2 *= ls; x3 *= ls;
    }

    float4 o = make_float4(x0, x1, x2, x3);
    *(float4*)(xout + (size_t)warp * DD + lane * 4) = o;
}

// ---------------------------------------------------------------------------
extern "C" void kernel_launch(void* const* d_in, const int* in_sizes, int n_in,
                              void* d_out, int out_size) {
    const float* node_repr = (const float*)d_in[0];
    const int*   adj       = (const int*)  d_in[1];
    const float* weight    = (const float*)d_in[2];
    const float* mask      = (const float*)d_in[3];
    const float* msg_w     = (const float*)d_in[4];

    int N = in_sizes[0] / DD;
    float* out = (float*)d_out;

    float*  xbuf;
    __half* mbuf;
    cudaGetSymbolAddress((void**)&xbuf, g_x);
    cudaGetSymbolAddress((void**)&mbuf, g_msg);

    int warpBlocks = (N * 32 + 255) / 256;
    int gemmBlocks = (N + 127) / 128;

    // ---- Layer 0 ----  (prep fused: mask into GEMM A-load)
    gemm_kernel<true><<<gemmBlocks, 256>>>(node_repr, msg_w, mask, mbuf, N);
    // gather with fused exp-map/relu AND next layer's log-map prep
    gather_kernel<true><<<warpBlocks, 256>>>(adj, weight, mask, mbuf, xbuf, N);

    // ---- Layer 1 ----  (A already in tangent space with mask applied)
    gemm_kernel<false><<<gemmBlocks, 256>>>(xbuf, msg_w + DD * DD, mask, mbuf, N);
    gather_kernel<false><<<warpBlocks, 256>>>(adj, weight, mask, mbuf, out, N);
}

// round 4
// speedup vs baseline: 2.6937x; 1.4412x over previous
#include <cuda_runtime.h>
#include <cuda_fp16.h>
#include <cstdint>
#include <math.h>

#define DD 128
#define KK 32
#define NMAX 50000

// Scratch (allocation-free rule: __device__ globals)
__device__ float  g_x[NMAX * DD];     // tangent-space features for layer-1 GEMM
__device__ __half g_msg[NMAX * DD];   // GEMM output (messages), fp16

__device__ __forceinline__ unsigned int f2tf32(float f) {
    unsigned int u;
    asm("cvt.rna.tf32.f32 %0, %1;" : "=r"(u) : "f"(f));
    return u;
}

// ---------------------------------------------------------------------------
// Tensor-core GEMM: C[N,128] = (A * opt rowmask) @ W[128,128], * mask[row],
// output fp16. mma.sync.m16n8k8 tf32, fp32 accumulate.
// 256 threads = 8 warps as 4(row) x 2(col); warp tile 32x64 = 2x8 atoms.
// Shared: As[row][k] stride 36 (frag loads bank = lane, conflict-free),
//         Ws[k][col] stride 136 (bank = 8*(lane%4)+lane/4, conflict-free).
// ---------------------------------------------------------------------------
#define SA 36
#define SW 136

template <bool SCALE_A>
__global__ __launch_bounds__(256, 2)
void gemm_tc_kernel(const float* __restrict__ A,
                    const float* __restrict__ W,
                    const float* __restrict__ mask,
                    __half* __restrict__ C,
                    int N) {
    __shared__ unsigned int As[128 * SA];
    __shared__ unsigned int Ws[32 * SW];

    int tid  = threadIdx.x;
    int lane = tid & 31;
    int warp = tid >> 5;
    int wr   = warp >> 1;          // 0..3
    int wc   = warp & 1;           // 0..1
    int g    = lane >> 2;          // 0..7
    int tg   = lane & 3;           // 0..3

    int block_row = blockIdx.x * 128;

    float acc[2][8][4];
    #pragma unroll
    for (int ma = 0; ma < 2; ma++)
        #pragma unroll
        for (int na = 0; na < 8; na++)
            #pragma unroll
            for (int i = 0; i < 4; i++) acc[ma][na][i] = 0.f;

    for (int k0 = 0; k0 < 128; k0 += 32) {
        // A tile: 128 rows x 32 k. 1024 float4, 4 per thread.
        #pragma unroll
        for (int i = 0; i < 4; i++) {
            int idx  = tid + i * 256;
            int row  = idx >> 3;           // 0..127
            int c4   = idx & 7;            // 0..7
            int grow = block_row + row;
            float4 v = make_float4(0.f, 0.f, 0.f, 0.f);
            if (grow < N) {
                v = *(const float4*)(A + (size_t)grow * 128 + k0 + c4 * 4);
                if (SCALE_A) {
                    float m = mask[grow];
                    v.x *= m; v.y *= m; v.z *= m; v.w *= m;
                }
            }
            uint4 u;
            u.x = f2tf32(v.x); u.y = f2tf32(v.y);
            u.z = f2tf32(v.z); u.w = f2tf32(v.w);
            *(uint4*)&As[row * SA + c4 * 4] = u;
        }
        // W tile: 32 k x 128 cols. 1024 float4, 4 per thread.
        #pragma unroll
        for (int i = 0; i < 4; i++) {
            int idx = tid + i * 256;
            int kr  = idx >> 5;            // 0..31
            int c4  = idx & 31;            // 0..31
            float4 v = *(const float4*)(W + (size_t)(k0 + kr) * 128 + c4 * 4);
            uint4 u;
            u.x = f2tf32(v.x); u.y = f2tf32(v.y);
            u.z = f2tf32(v.z); u.w = f2tf32(v.w);
            *(uint4*)&Ws[kr * SW + c4 * 4] = u;
        }
        __syncthreads();

        #pragma unroll
        for (int ks = 0; ks < 4; ks++) {
            int k8 = ks * 8;
            unsigned int af[2][4];
            #pragma unroll
            for (int ma = 0; ma < 2; ma++) {
                int r = wr * 32 + ma * 16;
                af[ma][0] = As[(r + g)     * SA + k8 + tg];
                af[ma][1] = As[(r + g + 8) * SA + k8 + tg];
                af[ma][2] = As[(r + g)     * SA + k8 + tg + 4];
                af[ma][3] = As[(r + g + 8) * SA + k8 + tg + 4];
            }
            unsigned int bf[8][2];
            #pragma unroll
            for (int na = 0; na < 8; na++) {
                int cc = wc * 64 + na * 8 + g;
                bf[na][0] = Ws[(k8 + tg)     * SW + cc];
                bf[na][1] = Ws[(k8 + tg + 4) * SW + cc];
            }
            #pragma unroll
            for (int ma = 0; ma < 2; ma++)
                #pragma unroll
                for (int na = 0; na < 8; na++) {
                    asm volatile(
                        "mma.sync.aligned.m16n8k8.row.col.f32.tf32.tf32.f32 "
                        "{%0,%1,%2,%3}, {%4,%5,%6,%7}, {%8,%9}, {%0,%1,%2,%3};\n"
                        : "+f"(acc[ma][na][0]), "+f"(acc[ma][na][1]),
                          "+f"(acc[ma][na][2]), "+f"(acc[ma][na][3])
                        : "r"(af[ma][0]), "r"(af[ma][1]),
                          "r"(af[ma][2]), "r"(af[ma][3]),
                          "r"(bf[na][0]), "r"(bf[na][1]));
                }
        }
        __syncthreads();
    }

    // Epilogue: * mask[row], fp16 stores (half2 per c-pair)
    #pragma unroll
    for (int ma = 0; ma < 2; ma++) {
        int r0g = block_row + wr * 32 + ma * 16 + g;   // c0/c1 row
        int r1g = r0g + 8;                             // c2/c3 row
        float m0 = (r0g < N) ? mask[r0g] : 0.f;
        float m1 = (r1g < N) ? mask[r1g] : 0.f;
        #pragma unroll
        for (int na = 0; na < 8; na++) {
            int col = wc * 64 + na * 8 + 2 * tg;
            if (r0g < N) {
                __half2 h = __floats2half2_rn(acc[ma][na][0] * m0,
                                              acc[ma][na][1] * m0);
                *(__half2*)(C + (size_t)r0g * 128 + col) = h;
            }
            if (r1g < N) {
                __half2 h = __floats2half2_rn(acc[ma][na][2] * m1,
                                              acc[ma][na][3] * m1);
                *(__half2*)(C + (size_t)r1g * 128 + col) = h;
            }
        }
    }
}

// ---------------------------------------------------------------------------
// Gather (fp16 msg) + weighted sum + exp-map + ReLU [+ fused next-layer
// log-map]. One warp per node; lane owns 4 columns.
// ---------------------------------------------------------------------------
template <bool FUSE_LOGMAP>
__global__ void gather_kernel(const int*    __restrict__ adj,
                              const float*  __restrict__ wgt,
                              const float*  __restrict__ mask,
                              const __half* __restrict__ msg,
                              float* __restrict__ xout,
                              int N) {
    int warp = (blockIdx.x * blockDim.x + threadIdx.x) >> 5;
    int lane = threadIdx.x & 31;
    if (warp >= N) return;

    int   a = adj[(size_t)warp * KK + lane];
    float w = wgt[(size_t)warp * KK + lane];

    float acc0 = 0.f, acc1 = 0.f, acc2 = 0.f, acc3 = 0.f;
    #pragma unroll
    for (int k = 0; k < KK; k++) {
        int   j  = __shfl_sync(0xffffffffu, a, k);
        float wk = __shfl_sync(0xffffffffu, w, k);
        uint2 raw = *(const uint2*)(msg + (size_t)j * DD + lane * 4);
        float2 f0 = __half22float2(*(__half2*)&raw.x);
        float2 f1 = __half22float2(*(__half2*)&raw.y);
        acc0 = fmaf(wk, f0.x, acc0);
        acc1 = fmaf(wk, f0.y, acc1);
        acc2 = fmaf(wk, f1.x, acc2);
        acc3 = fmaf(wk, f1.y, acc3);
    }

    float mk = mask[warp];
    acc0 *= mk; acc1 *= mk; acc2 *= mk; acc3 *= mk;   // combined

    float s = acc0 * acc0 + acc1 * acc1 + acc2 * acc2 + acc3 * acc3;
    #pragma unroll
    for (int o = 16; o > 0; o >>= 1) s += __shfl_xor_sync(0xffffffffu, s, o);
    float n  = sqrtf(s);
    float nc = fminf(fmaxf(n, 1e-5f), 15.0f);
    float scale = tanhf(nc) / fmaxf(n, 1e-5f) * mk;   // expmap * mask

    float x0 = fmaxf(acc0 * scale, 0.f) * mk;         // relu * mask
    float x1 = fmaxf(acc1 * scale, 0.f) * mk;
    float x2 = fmaxf(acc2 * scale, 0.f) * mk;
    float x3 = fmaxf(acc3 * scale, 0.f) * mk;

    if (FUSE_LOGMAP) {
        float s2 = x0 * x0 + x1 * x1 + x2 * x2 + x3 * x3;
        #pragma unroll
        for (int o = 16; o > 0; o >>= 1) s2 += __shfl_xor_sync(0xffffffffu, s2, o);
        float n2  = sqrtf(s2);
        float nc2 = fminf(fmaxf(n2, 1e-5f), 1.0f - 1e-5f);
        float ls  = atanhf(nc2) / fmaxf(n2, 1e-5f) * mk;
        x0 *= ls; x1 *= ls; x2 *= ls; x3 *= ls;
    }

    float4 o = make_float4(x0, x1, x2, x3);
    *(float4*)(xout + (size_t)warp * DD + lane * 4) = o;
}

// ---------------------------------------------------------------------------
extern "C" void kernel_launch(void* const* d_in, const int* in_sizes, int n_in,
                              void* d_out, int out_size) {
    const float* node_repr = (const float*)d_in[0];
    const int*   adj       = (const int*)  d_in[1];
    const float* weight    = (const float*)d_in[2];
    const float* mask      = (const float*)d_in[3];
    const float* msg_w     = (const float*)d_in[4];

    int N = in_sizes[0] / DD;
    float* out = (float*)d_out;

    float*  xbuf;
    __half* mbuf;
    cudaGetSymbolAddress((void**)&xbuf, g_x);
    cudaGetSymbolAddress((void**)&mbuf, g_msg);

    int warpBlocks = (N * 32 + 255) / 256;
    int gemmBlocks = (N + 127) / 128;

    // ---- Layer 0 ----  (mask folded into GEMM A-load)
    gemm_tc_kernel<true><<<gemmBlocks, 256>>>(node_repr, msg_w, mask, mbuf, N);
    gather_kernel<true><<<warpBlocks, 256>>>(adj, weight, mask, mbuf, xbuf, N);

    // ---- Layer 1 ----  (xbuf already tangent-space * mask)
    gemm_tc_kernel<false><<<gemmBlocks, 256>>>(xbuf, msg_w + DD * DD, mask, mbuf, N);
    gather_kernel<false><<<warpBlocks, 256>>>(adj, weight, mask, mbuf, out, N);
}

// round 5
// speedup vs baseline: 3.0269x; 1.1237x over previous
#include <cuda_runtime.h>
#include <cuda_fp16.h>
#include <cstdint>
#include <math.h>

#define DD 128
#define KK 32
#define NMAX 50000

// Scratch (allocation-free rule: __device__ globals)
__device__ float  g_x[NMAX * DD];     // tangent-space features for layer-1 GEMM
__device__ __half g_msg[NMAX * DD];   // GEMM output (messages), fp16

// ---------------------------------------------------------------------------
// cp.async 16B helper (pred=false -> zero-fill)
// ---------------------------------------------------------------------------
__device__ __forceinline__ void cp16(void* dst_smem, const void* src, bool pred) {
    unsigned sdst = (unsigned)__cvta_generic_to_shared(dst_smem);
    int sz = pred ? 16 : 0;
    asm volatile("cp.async.cg.shared.global [%0], [%1], 16, %2;\n"
                 :: "r"(sdst), "l"(src), "r"(sz));
}

// ---------------------------------------------------------------------------
// Tensor-core GEMM: C[N,128] = A @ W[128,128], epilogue * mask^MPOW, fp16 out.
// mma.sync.m16n8k8 tf32 (raw f32 bits, HW-truncated), fp32 accumulate.
// 2-stage cp.async pipeline, BK=16 (8 iterations).
// 256 threads = 8 warps as 4(row) x 2(col); warp tile 32x64 = 2x8 atoms.
// As[row][k] stride 20, Ws[k][col] stride 136: both conflict-free.
// ---------------------------------------------------------------------------
#define BK 16
#define SA 20
#define SW 136

template <int MPOW>   // epilogue multiplies by mask[row]^MPOW
__global__ __launch_bounds__(256, 2)
void gemm_tc_kernel(const float* __restrict__ A,
                    const float* __restrict__ W,
                    const float* __restrict__ mask,
                    __half* __restrict__ C,
                    int N) {
    __shared__ float As[2][128 * SA];
    __shared__ float Ws[2][BK * SW];

    int tid  = threadIdx.x;
    int lane = tid & 31;
    int warp = tid >> 5;
    int wr   = warp >> 1;          // 0..3
    int wc   = warp & 1;           // 0..1
    int g    = lane >> 2;          // 0..7
    int tg   = lane & 3;           // 0..3

    int block_row = blockIdx.x * 128;

    float acc[2][8][4];
    #pragma unroll
    for (int ma = 0; ma < 2; ma++)
        #pragma unroll
        for (int na = 0; na < 8; na++)
            #pragma unroll
            for (int i = 0; i < 4; i++) acc[ma][na][i] = 0.f;

    // ---- stage loader: A tile 128x16 (512 f4, 2/thr), W tile 16x128 ----
    #define LOAD_TILES(s, k0)                                                  \
    {                                                                          \
        _Pragma("unroll")                                                      \
        for (int i = 0; i < 2; i++) {                                          \
            int idx  = tid + i * 256;                                          \
            int row  = idx >> 2;                                               \
            int c4   = idx & 3;                                                \
            int grow = block_row + row;                                        \
            cp16(&As[s][row * SA + c4 * 4],                                    \
                 A + (size_t)grow * 128 + (k0) + c4 * 4, grow < N);            \
        }                                                                      \
        _Pragma("unroll")                                                      \
        for (int i = 0; i < 2; i++) {                                          \
            int idx = tid + i * 256;                                           \
            int kr  = idx >> 5;                                                \
            int c4  = idx & 31;                                                \
            cp16(&Ws[s][kr * SW + c4 * 4],                                     \
                 W + (size_t)((k0) + kr) * 128 + c4 * 4, true);                \
        }                                                                      \
        asm volatile("cp.async.commit_group;\n");                              \
    }

    LOAD_TILES(0, 0);

    #pragma unroll
    for (int it = 0; it < 8; it++) {
        int s = it & 1;
        if (it < 7) LOAD_TILES(s ^ 1, (it + 1) * BK);
        if (it < 7) asm volatile("cp.async.wait_group 1;\n");
        else        asm volatile("cp.async.wait_group 0;\n");
        __syncthreads();

        #pragma unroll
        for (int ks = 0; ks < 2; ks++) {
            int k8 = ks * 8;
            unsigned int af[2][4];
            #pragma unroll
            for (int ma = 0; ma < 2; ma++) {
                int r = wr * 32 + ma * 16;
                const unsigned int* Asu = (const unsigned int*)As[s];
                af[ma][0] = Asu[(r + g)     * SA + k8 + tg];
                af[ma][1] = Asu[(r + g + 8) * SA + k8 + tg];
                af[ma][2] = Asu[(r + g)     * SA + k8 + tg + 4];
                af[ma][3] = Asu[(r + g + 8) * SA + k8 + tg + 4];
            }
            unsigned int bf[8][2];
            #pragma unroll
            for (int na = 0; na < 8; na++) {
                int cc = wc * 64 + na * 8 + g;
                const unsigned int* Wsu = (const unsigned int*)Ws[s];
                bf[na][0] = Wsu[(k8 + tg)     * SW + cc];
                bf[na][1] = Wsu[(k8 + tg + 4) * SW + cc];
            }
            #pragma unroll
            for (int ma = 0; ma < 2; ma++)
                #pragma unroll
                for (int na = 0; na < 8; na++) {
                    asm volatile(
                        "mma.sync.aligned.m16n8k8.row.col.f32.tf32.tf32.f32 "
                        "{%0,%1,%2,%3}, {%4,%5,%6,%7}, {%8,%9}, {%0,%1,%2,%3};\n"
                        : "+f"(acc[ma][na][0]), "+f"(acc[ma][na][1]),
                          "+f"(acc[ma][na][2]), "+f"(acc[ma][na][3])
                        : "r"(af[ma][0]), "r"(af[ma][1]),
                          "r"(af[ma][2]), "r"(af[ma][3]),
                          "r"(bf[na][0]), "r"(bf[na][1]));
                }
        }
        __syncthreads();
    }

    // Epilogue: * mask^MPOW, fp16 stores
    #pragma unroll
    for (int ma = 0; ma < 2; ma++) {
        int r0g = block_row + wr * 32 + ma * 16 + g;
        int r1g = r0g + 8;
        float m0 = (r0g < N) ? mask[r0g] : 0.f;
        float m1 = (r1g < N) ? mask[r1g] : 0.f;
        if (MPOW == 2) { m0 *= m0; m1 *= m1; }
        #pragma unroll
        for (int na = 0; na < 8; na++) {
            int col = wc * 64 + na * 8 + 2 * tg;
            if (r0g < N) {
                __half2 h = __floats2half2_rn(acc[ma][na][0] * m0,
                                              acc[ma][na][1] * m0);
                *(__half2*)(C + (size_t)r0g * 128 + col) = h;
            }
            if (r1g < N) {
                __half2 h = __floats2half2_rn(acc[ma][na][2] * m1,
                                              acc[ma][na][3] * m1);
                *(__half2*)(C + (size_t)r1g * 128 + col) = h;
            }
        }
    }
}

// ---------------------------------------------------------------------------
// Gather (fp16 msg) + weighted sum + exp-map + ReLU [+ fused next-layer
// log-map]. One warp per node; lane owns 4 columns. (adj,w) pairs staged in
// shared (LDS.64 broadcast replaces 2x SHFL); packed fma.rn.f32x2 accumulate.
// ---------------------------------------------------------------------------
template <bool FUSE_LOGMAP>
__global__ void gather_kernel(const int*    __restrict__ adj,
                              const float*  __restrict__ wgt,
                              const float*  __restrict__ mask,
                              const __half* __restrict__ msg,
                              float* __restrict__ xout,
                              int N) {
    __shared__ int2 pairs[8][KK];

    int tid  = threadIdx.x;
    int warp = tid >> 5;
    int lane = tid & 31;
    int gnode = blockIdx.x * 8 + warp;
    if (gnode >= N) return;

    // each warp stages its own node's (adj, w) row
    pairs[warp][lane].x = adj[(size_t)gnode * KK + lane];
    pairs[warp][lane].y = __float_as_int(wgt[(size_t)gnode * KK + lane]);
    __syncwarp();

    unsigned long long acc01 = 0ull, acc23 = 0ull;   // f32x2 accumulators
    #pragma unroll
    for (int k = 0; k < KK; k++) {
        int2 p = pairs[warp][k];                     // LDS.64 broadcast
        float wk = __int_as_float(p.y);
        unsigned long long w2, m01, m23;
        asm("mov.b64 %0, {%1,%1};" : "=l"(w2) : "f"(wk));
        uint2 raw = *(const uint2*)(msg + (size_t)p.x * DD + lane * 4);
        float2 f0 = __half22float2(*(__half2*)&raw.x);
        float2 f1 = __half22float2(*(__half2*)&raw.y);
        asm("mov.b64 %0, {%1,%2};" : "=l"(m01) : "f"(f0.x), "f"(f0.y));
        asm("mov.b64 %0, {%1,%2};" : "=l"(m23) : "f"(f1.x), "f"(f1.y));
        asm("fma.rn.f32x2 %0, %1, %2, %0;" : "+l"(acc01) : "l"(m01), "l"(w2));
        asm("fma.rn.f32x2 %0, %1, %2, %0;" : "+l"(acc23) : "l"(m23), "l"(w2));
    }
    float acc0, acc1, acc2, acc3;
    asm("mov.b64 {%0,%1}, %2;" : "=f"(acc0), "=f"(acc1) : "l"(acc01));
    asm("mov.b64 {%0,%1}, %2;" : "=f"(acc2), "=f"(acc3) : "l"(acc23));

    float mk = mask[gnode];
    acc0 *= mk; acc1 *= mk; acc2 *= mk; acc3 *= mk;   // combined

    float s = acc0 * acc0 + acc1 * acc1 + acc2 * acc2 + acc3 * acc3;
    #pragma unroll
    for (int o = 16; o > 0; o >>= 1) s += __shfl_xor_sync(0xffffffffu, s, o);
    float n  = sqrtf(s);
    float nc = fminf(fmaxf(n, 1e-5f), 15.0f);
    float scale = tanhf(nc) / fmaxf(n, 1e-5f) * mk;   // expmap * mask

    float x0 = fmaxf(acc0 * scale, 0.f) * mk;         // relu * mask
    float x1 = fmaxf(acc1 * scale, 0.f) * mk;
    float x2 = fmaxf(acc2 * scale, 0.f) * mk;
    float x3 = fmaxf(acc3 * scale, 0.f) * mk;

    if (FUSE_LOGMAP) {
        float s2 = x0 * x0 + x1 * x1 + x2 * x2 + x3 * x3;
        #pragma unroll
        for (int o = 16; o > 0; o >>= 1) s2 += __shfl_xor_sync(0xffffffffu, s2, o);
        float n2  = sqrtf(s2);
        float nc2 = fminf(fmaxf(n2, 1e-5f), 1.0f - 1e-5f);
        float ls  = atanhf(nc2) / fmaxf(n2, 1e-5f) * mk;
        x0 *= ls; x1 *= ls; x2 *= ls; x3 *= ls;
    }

    float4 o = make_float4(x0, x1, x2, x3);
    *(float4*)(xout + (size_t)gnode * DD + lane * 4) = o;
}

// ---------------------------------------------------------------------------
extern "C" void kernel_launch(void* const* d_in, const int* in_sizes, int n_in,
                              void* d_out, int out_size) {
    const float* node_repr = (const float*)d_in[0];
    const int*   adj       = (const int*)  d_in[1];
    const float* weight    = (const float*)d_in[2];
    const float* mask      = (const float*)d_in[3];
    const float* msg_w     = (const float*)d_in[4];

    int N = in_sizes[0] / DD;
    float* out = (float*)d_out;

    float*  xbuf;
    __half* mbuf;
    cudaGetSymbolAddress((void**)&xbuf, g_x);
    cudaGetSymbolAddress((void**)&mbuf, g_msg);

    int warpBlocks = (N + 7) / 8;
    int gemmBlocks = (N + 127) / 128;

    // ---- Layer 0 ----  (mask applied as mask^2 in epilogue: (x*m)@W*m = m^2*(x@W))
    gemm_tc_kernel<2><<<gemmBlocks, 256>>>(node_repr, msg_w, mask, mbuf, N);
    gather_kernel<true><<<warpBlocks, 256>>>(adj, weight, mask, mbuf, xbuf, N);

    // ---- Layer 1 ----  (xbuf already tangent-space * mask)
    gemm_tc_kernel<1><<<gemmBlocks, 256>>>(xbuf, msg_w + DD * DD, mask, mbuf, N);
    gather_kernel<false><<<warpBlocks, 256>>>(adj, weight, mask, mbuf, out, N);
}

// round 7
// speedup vs baseline: 3.3952x; 1.1217x over previous
#include <cuda_runtime.h>
#include <cuda_fp16.h>
#include <cstdint>
#include <math.h>

#define DD 128
#define KK 32
#define NMAX 50000

// Scratch (allocation-free rule: __device__ globals)
__device__ float  g_x[NMAX * DD];     // tangent-space features for layer-1 GEMM
__device__ __half g_msg[NMAX * DD];   // GEMM output (messages), fp16

// ---------------------------------------------------------------------------
// cp.async 16B helper (pred=false -> zero-fill)
// ---------------------------------------------------------------------------
__device__ __forceinline__ void cp16(void* dst_smem, const void* src, bool pred) {
    unsigned sdst = (unsigned)__cvta_generic_to_shared(dst_smem);
    int sz = pred ? 16 : 0;
    asm volatile("cp.async.cg.shared.global [%0], [%1], 16, %2;\n"
                 :: "r"(sdst), "l"(src), "r"(sz));
}

// ---------------------------------------------------------------------------
// Tensor-core GEMM: C[N,128] = A @ W[128,128], epilogue * mask^MPOW, fp16 out.
// mma.sync.m16n8k8 tf32, fp32 accumulate. 2-stage cp.async pipeline, BK=16.
// 256 threads = 8 warps as 4(row) x 2(col); warp tile 32x64 = 2x8 atoms.
// ---------------------------------------------------------------------------
#define BK 16
#define SA 20
#define SW 136

template <int MPOW>
__global__ __launch_bounds__(256, 2)
void gemm_tc_kernel(const float* __restrict__ A,
                    const float* __restrict__ W,
                    const float* __restrict__ mask,
                    __half* __restrict__ C,
                    int N) {
    __shared__ float As[2][128 * SA];
    __shared__ float Ws[2][BK * SW];

    int tid  = threadIdx.x;
    int lane = tid & 31;
    int warp = tid >> 5;
    int wr   = warp >> 1;
    int wc   = warp & 1;
    int g    = lane >> 2;
    int tg   = lane & 3;

    int block_row = blockIdx.x * 128;

    float acc[2][8][4];
    #pragma unroll
    for (int ma = 0; ma < 2; ma++)
        #pragma unroll
        for (int na = 0; na < 8; na++)
            #pragma unroll
            for (int i = 0; i < 4; i++) acc[ma][na][i] = 0.f;

    #define LOAD_TILES(s, k0)                                                  \
    {                                                                          \
        _Pragma("unroll")                                                      \
        for (int i = 0; i < 2; i++) {                                          \
            int idx  = tid + i * 256;                                          \
            int row  = idx >> 2;                                               \
            int c4   = idx & 3;                                                \
            int grow = block_row + row;                                        \
            cp16(&As[s][row * SA + c4 * 4],                                    \
                 A + (size_t)grow * 128 + (k0) + c4 * 4, grow < N);            \
        }                                                                      \
        _Pragma("unroll")                                                      \
        for (int i = 0; i < 2; i++) {                                          \
            int idx = tid + i * 256;                                           \
            int kr  = idx >> 5;                                                \
            int c4  = idx & 31;                                                \
            cp16(&Ws[s][kr * SW + c4 * 4],                                     \
                 W + (size_t)((k0) + kr) * 128 + c4 * 4, true);                \
        }                                                                      \
        asm volatile("cp.async.commit_group;\n");                              \
    }

    LOAD_TILES(0, 0);

    #pragma unroll
    for (int it = 0; it < 8; it++) {
        int s = it & 1;
        if (it < 7) LOAD_TILES(s ^ 1, (it + 1) * BK);
        if (it < 7) asm volatile("cp.async.wait_group 1;\n");
        else        asm volatile("cp.async.wait_group 0;\n");
        __syncthreads();

        #pragma unroll
        for (int ks = 0; ks < 2; ks++) {
            int k8 = ks * 8;
            unsigned int af[2][4];
            #pragma unroll
            for (int ma = 0; ma < 2; ma++) {
                int r = wr * 32 + ma * 16;
                const unsigned int* Asu = (const unsigned int*)As[s];
                af[ma][0] = Asu[(r + g)     * SA + k8 + tg];
                af[ma][1] = Asu[(r + g + 8) * SA + k8 + tg];
                af[ma][2] = Asu[(r + g)     * SA + k8 + tg + 4];
                af[ma][3] = Asu[(r + g + 8) * SA + k8 + tg + 4];
            }
            unsigned int bf[8][2];
            #pragma unroll
            for (int na = 0; na < 8; na++) {
                int cc = wc * 64 + na * 8 + g;
                const unsigned int* Wsu = (const unsigned int*)Ws[s];
                bf[na][0] = Wsu[(k8 + tg)     * SW + cc];
                bf[na][1] = Wsu[(k8 + tg + 4) * SW + cc];
            }
            #pragma unroll
            for (int ma = 0; ma < 2; ma++)
                #pragma unroll
                for (int na = 0; na < 8; na++) {
                    asm volatile(
                        "mma.sync.aligned.m16n8k8.row.col.f32.tf32.tf32.f32 "
                        "{%0,%1,%2,%3}, {%4,%5,%6,%7}, {%8,%9}, {%0,%1,%2,%3};\n"
                        : "+f"(acc[ma][na][0]), "+f"(acc[ma][na][1]),
                          "+f"(acc[ma][na][2]), "+f"(acc[ma][na][3])
                        : "r"(af[ma][0]), "r"(af[ma][1]),
                          "r"(af[ma][2]), "r"(af[ma][3]),
                          "r"(bf[na][0]), "r"(bf[na][1]));
                }
        }
        __syncthreads();
    }

    #pragma unroll
    for (int ma = 0; ma < 2; ma++) {
        int r0g = block_row + wr * 32 + ma * 16 + g;
        int r1g = r0g + 8;
        float m0 = (r0g < N) ? mask[r0g] : 0.f;
        float m1 = (r1g < N) ? mask[r1g] : 0.f;
        if (MPOW == 2) { m0 *= m0; m1 *= m1; }
        #pragma unroll
        for (int na = 0; na < 8; na++) {
            int col = wc * 64 + na * 8 + 2 * tg;
            if (r0g < N) {
                __half2 h = __floats2half2_rn(acc[ma][na][0] * m0,
                                              acc[ma][na][1] * m0);
                *(__half2*)(C + (size_t)r0g * 128 + col) = h;
            }
            if (r1g < N) {
                __half2 h = __floats2half2_rn(acc[ma][na][2] * m1,
                                              acc[ma][na][3] * m1);
                *(__half2*)(C + (size_t)r1g * 128 + col) = h;
            }
        }
    }
}

// ---------------------------------------------------------------------------
// Gather v2: 2 nodes per warp, 16 lanes per node, 8 columns per lane.
// LDG.128 per lane per k (16 lanes x 16B = full 256B row, coalesced).
// (adj,w) pairs staged in shared; LDS.64 broadcast per half-warp.
// Fused weighted-sum + exp-map + ReLU [+ next-layer log-map].
// ---------------------------------------------------------------------------
template <bool FUSE_LOGMAP>
__global__ __launch_bounds__(256)
void gather_kernel(const int*    __restrict__ adj,
                   const float*  __restrict__ wgt,
                   const float*  __restrict__ mask,
                   const __half* __restrict__ msg,
                   float* __restrict__ xout,
                   int N) {
    __shared__ int2 pairs[8][2][KK];    // [warp][node-half][k]

    int tid   = threadIdx.x;
    int warp  = tid >> 5;
    int lane  = tid & 31;
    int half  = lane >> 4;              // which node within warp
    int hl    = lane & 15;              // lane within node (owns 8 cols)
    int node0 = blockIdx.x * 16 + warp * 2;
    int gnode = node0 + half;

    // stage both nodes' (adj, w) rows: 64 pairs per warp, 2 per lane
    #pragma unroll
    for (int i = 0; i < 2; i++) {
        int idx = lane + i * 32;        // 0..63
        int h   = idx >> 5;             // node half
        int k   = idx & 31;
        int gn  = node0 + h;
        if (gn < N) {
            pairs[warp][h][k].x = adj[(size_t)gn * KK + k];
            pairs[warp][h][k].y = __float_as_int(wgt[(size_t)gn * KK + k]);
        }
    }
    __syncwarp();
    if (gnode >= N) return;

    float acc[8];
    #pragma unroll
    for (int i = 0; i < 8; i++) acc[i] = 0.f;

    #pragma unroll
    for (int k = 0; k < KK; k++) {
        int2 p = pairs[warp][half][k];            // LDS.64 broadcast (16 lanes)
        float wk = __int_as_float(p.y);
        uint4 raw = *(const uint4*)(msg + (size_t)p.x * DD + hl * 8);
        float2 f0 = __half22float2(*(__half2*)&raw.x);
        float2 f1 = __half22float2(*(__half2*)&raw.y);
        float2 f2 = __half22float2(*(__half2*)&raw.z);
        float2 f3 = __half22float2(*(__half2*)&raw.w);
        acc[0] = fmaf(wk, f0.x, acc[0]);
        acc[1] = fmaf(wk, f0.y, acc[1]);
        acc[2] = fmaf(wk, f1.x, acc[2]);
        acc[3] = fmaf(wk, f1.y, acc[3]);
        acc[4] = fmaf(wk, f2.x, acc[4]);
        acc[5] = fmaf(wk, f2.y, acc[5]);
        acc[6] = fmaf(wk, f3.x, acc[6]);
        acc[7] = fmaf(wk, f3.y, acc[7]);
    }

    float mk = mask[gnode];
    #pragma unroll
    for (int i = 0; i < 8; i++) acc[i] *= mk;     // combined

    // exp-map at origin (norm over this node's 16 lanes x 8 cols)
    float s = 0.f;
    #pragma unroll
    for (int i = 0; i < 8; i++) s = fmaf(acc[i], acc[i], s);
    #pragma unroll
    for (int o = 8; o > 0; o >>= 1) s += __shfl_xor_sync(0xffffffffu, s, o);
    float n  = sqrtf(s);
    float nc = fminf(fmaxf(n, 1e-5f), 15.0f);
    float scale = tanhf(nc) / fmaxf(n, 1e-5f) * mk;   // expmap * mask

    float x[8];
    #pragma unroll
    for (int i = 0; i < 8; i++) x[i] = fmaxf(acc[i] * scale, 0.f) * mk;

    if (FUSE_LOGMAP) {
        float s2 = 0.f;
        #pragma unroll
        for (int i = 0; i < 8; i++) s2 = fmaf(x[i], x[i], s2);
        #pragma unroll
        for (int o = 8; o > 0; o >>= 1) s2 += __shfl_xor_sync(0xffffffffu, s2, o);
        float n2  = sqrtf(s2);
        float nc2 = fminf(fmaxf(n2, 1e-5f), 1.0f - 1e-5f);
        float ls  = atanhf(nc2) / fmaxf(n2, 1e-5f) * mk;
        #pragma unroll
        for (int i = 0; i < 8; i++) x[i] *= ls;
    }

    float* dst = xout + (size_t)gnode * DD + hl * 8;
    *(float4*)(dst)     = make_float4(x[0], x[1], x[2], x[3]);
    *(float4*)(dst + 4) = make_float4(x[4], x[5], x[6], x[7]);
}

// ---------------------------------------------------------------------------
extern "C" void kernel_launch(void* const* d_in, const int* in_sizes, int n_in,
                              void* d_out, int out_size) {
    const float* node_repr = (const float*)d_in[0];
    const int*   adj       = (const int*)  d_in[1];
    const float* weight    = (const float*)d_in[2];
    const float* mask      = (const float*)d_in[3];
    const float* msg_w     = (const float*)d_in[4];

    int N = in_sizes[0] / DD;
    float* out = (float*)d_out;

    float*  xbuf;
    __half* mbuf;
    cudaGetSymbolAddress((void**)&xbuf, g_x);
    cudaGetSymbolAddress((void**)&mbuf, g_msg);

    int gatherBlocks = (N + 15) / 16;       // 16 nodes per 256-thread block
    int gemmBlocks   = (N + 127) / 128;

    // ---- Layer 0 ----  ((x*m)@W*m = m^2*(x@W): mask^2 in epilogue)
    gemm_tc_kernel<2><<<gemmBlocks, 256>>>(node_repr, msg_w, mask, mbuf, N);
    gather_kernel<true><<<gatherBlocks, 256>>>(adj, weight, mask, mbuf, xbuf, N);

    // ---- Layer 1 ----  (xbuf already tangent-space * mask)
    gemm_tc_kernel<1><<<gemmBlocks, 256>>>(xbuf, msg_w + DD * DD, mask, mbuf, N);
    gather_kernel<false><<<gatherBlocks, 256>>>(adj, weight, mask, mbuf, out, N);
}